// round 5
// baseline (speedup 1.0000x reference)
#include <cuda_runtime.h>
#include <cuda_bf16.h>
#include <math.h>

// B=4, H=W=704, M=32, P=128, NN=129, R=1, GAIN=2.0
// Only batch b=3 contributes (reference returns losses[-1]).
// SINGLE WARP (32 threads). Per thread:
//   4 pos items  (t, t+32, t+64, t+96)
//   4 neg items  (t, t+32, t+64, t+96)   [+ item 128 on t==0]
//   1 reg item   (t)
// All index loads issue first, then all gathers (2-hop latency chain),
// then compute, then a 5-stage shuffle reduction. No smem, no barriers.

#define HH 704
#define WW 704
#define HWSZ (HH * WW)
#define BM 32
#define PP 128
#define NNEG 129
#define GAIN_F 2.0f

__device__ __forceinline__ float lse2(float a, float b) {
    float m = fmaxf(a, b);
    return m + __logf(__expf(a - m) + __expf(b - m));
}

__device__ __forceinline__ float smooth_l1(float d) {
    float a = fabsf(d);
    return (a < 1.0f) ? 0.5f * d * d : a - 0.5f;
}

__global__ void __launch_bounds__(32, 1) loss_total_kernel(
    const float* __restrict__ ref_boxes,     // (B,M,7)
    const float* __restrict__ pred_class,    // (B,4,H,W)
    const float* __restrict__ pred_regress,  // (B,14,H,W)
    const float* __restrict__ anchor,        // (2,7,H,W)
    const int*   __restrict__ pos_idx,       // (B,P,2)
    const int*   __restrict__ neg_idx,       // (B,NN,2)
    const int*   __restrict__ reg_idx,       // (B,M,1,2)
    float* __restrict__ out)
{
    const int t = threadIdx.x;

    // batch b=3 base offsets
    const float* pc = pred_class   + (size_t)3 * 4  * HWSZ;
    const float* pr = pred_regress + (size_t)3 * 14 * HWSZ;
    const float* rb = ref_boxes    + 3 * BM * 7;
    const int2*  pi = (const int2*)(pos_idx + 3 * PP * 2);
    const int2*  ni = (const int2*)(neg_idx + 3 * NNEG * 2);
    const int2*  ri = (const int2*)(reg_idx + 3 * BM * 2);

    // ---- hop 1: all index loads (independent, issue back-to-back) ----
    int2 ipos[4], ineg[4];
    #pragma unroll
    for (int i = 0; i < 4; i++) ipos[i] = pi[t + 32 * i];
    #pragma unroll
    for (int i = 0; i < 4; i++) ineg[i] = ni[t + 32 * i];
    int2 iextra = ni[(t == 0) ? 128 : 0];   // only t==0's value is used
    int2 ireg = ri[t];

    // ref box for this thread's reg item (independent of idx chain)
    float rv[7];
    #pragma unroll
    for (int c = 0; c < 7; c++) rv[c] = rb[t * 7 + c];

    // ---- hop 2: all gathers ----
    float LP[4][4], LN[4][4], LX[4];
    #pragma unroll
    for (int i = 0; i < 4; i++) {
        int off = ipos[i].x * WW + ipos[i].y;
        #pragma unroll
        for (int c = 0; c < 4; c++) LP[i][c] = pc[c * HWSZ + off];
    }
    #pragma unroll
    for (int i = 0; i < 4; i++) {
        int off = ineg[i].x * WW + ineg[i].y;
        #pragma unroll
        for (int c = 0; c < 4; c++) LN[i][c] = pc[c * HWSZ + off];
    }
    {
        int off = iextra.x * WW + iextra.y;
        #pragma unroll
        for (int c = 0; c < 4; c++) LX[c] = pc[c * HWSZ + off];
    }
    float av[14], pv[14];
    {
        int off = ireg.x * WW + ireg.y;
        #pragma unroll
        for (int c = 0; c < 14; c++) av[c] = anchor[(size_t)c * HWSZ + off];
        #pragma unroll
        for (int c = 0; c < 14; c++) pv[c] = pr[(size_t)c * HWSZ + off];
    }

    // ---- compute ----
    float local = 0.0f;

    // positives (label 1)
    #pragma unroll
    for (int i = 0; i < 4; i++) {
        local += ((lse2(LP[i][0], LP[i][1]) - LP[i][1]) +
                  (lse2(LP[i][2], LP[i][3]) - LP[i][3])) * (1.0f / (float)PP);
    }
    // negatives (label 0)
    #pragma unroll
    for (int i = 0; i < 4; i++) {
        local += ((lse2(LN[i][0], LN[i][1]) - LN[i][0]) +
                  (lse2(LN[i][2], LN[i][3]) - LN[i][2])) * (1.0f / (float)NNEG);
    }
    if (t == 0) {
        local += ((lse2(LX[0], LX[1]) - LX[0]) +
                  (lse2(LX[2], LX[3]) - LX[2])) * (1.0f / (float)NNEG);
    }

    // regression (R=1), 2 anchors x 7 channels
    float reg_m = 0.0f;
    #pragma unroll
    for (int a = 0; a < 2; a++) {
        const float* A = av + a * 7;
        const float* Pv = pv + a * 7;
        float inv_diag = rsqrtf(A[3] * A[3] + A[4] * A[4]);
        float o0 = (rv[0] - A[0]) * inv_diag;
        float o1 = (rv[1] - A[1]) * inv_diag;
        float o2 = (rv[2] - A[2]) / A[5];
        float o3 = __logf(rv[3] / A[3]);
        float o4 = __logf(rv[4] / A[4]);
        float o5 = __logf(rv[5] / A[5]);
        // arctan2(sin(dth), cos(dth)) == wrap dth into (-pi, pi]
        float dth = rv[6] - A[6];
        float o6 = dth - 6.28318530717958647692f *
                         rintf(dth * 0.15915494309189533577f);
        reg_m += smooth_l1(Pv[0] - o0) + smooth_l1(Pv[1] - o1) + smooth_l1(Pv[2] - o2)
               + smooth_l1(Pv[3] - o3) + smooth_l1(Pv[4] - o4) + smooth_l1(Pv[5] - o5)
               + smooth_l1(Pv[6] - o6);
    }
    local += GAIN_F * reg_m * (1.0f / 14.0f);

    // ---- warp shuffle reduction (no smem, no barriers) ----
    #pragma unroll
    for (int s = 16; s > 0; s >>= 1)
        local += __shfl_xor_sync(0xFFFFFFFFu, local, s);

    if (t == 0) out[0] = local;
}

extern "C" void kernel_launch(void* const* d_in, const int* in_sizes, int n_in,
                              void* d_out, int out_size) {
    const float* ref_boxes    = (const float*)d_in[0];
    const float* pred_class   = (const float*)d_in[1];
    const float* pred_regress = (const float*)d_in[2];
    const float* anchor       = (const float*)d_in[3];
    const int*   pos_idx      = (const int*)d_in[4];
    const int*   neg_idx      = (const int*)d_in[5];
    const int*   reg_idx      = (const int*)d_in[6];
    float* out = (float*)d_out;

    loss_total_kernel<<<1, 32>>>(ref_boxes, pred_class, pred_regress, anchor,
                                 pos_idx, neg_idx, reg_idx, out);
}